// round 3
// baseline (speedup 1.0000x reference)
#include <cuda_runtime.h>
#include <cuda_bf16.h>
#include <math.h>

#define N_NODES 50000
#define N_EDGES 800000
#define N_FEAT  128
#define DIM     32
#define N_GRAPHS 500
#define N_CLASSES 2

// ---------------- scratch (no allocations allowed) ----------------
__device__ float g_y[N_NODES * DIM];        // x @ w_rel
__device__ float g_z[N_NODES * DIM];        // x @ w_root
__device__ float g_pooled[N_GRAPHS * DIM];
__device__ int   g_deg[N_NODES];
__device__ int   g_off[N_NODES + 1];
__device__ int   g_cursor[N_NODES];
__device__ int2  g_csr[N_EDGES];            // (src, weight bits) sorted by dst
__device__ int   g_idx_is64;                // 1 if index buffers are int64

// ---------------- kernel 0: detect index dtype ----------------
// int64 little-endian -> every odd 32-bit word is the hi word of id<50000 -> 0.
__global__ void detect_kernel(const int* __restrict__ ei_raw) {
    __shared__ int s_any;
    if (threadIdx.x == 0) s_any = 0;
    __syncthreads();
    if (ei_raw[threadIdx.x * 2 + 1] != 0) atomicOr(&s_any, 1);
    __syncthreads();
    if (threadIdx.x == 0) g_idx_is64 = s_any ? 0 : 1;
}

// ---------------- kernel 1: projection (weights in registers) ----------------
// block = 256 threads = 8 warps = 2 quads. Each quad handles 16 nodes, with
// each of its 4 warps owning a 32-wide k-slice (weights held in registers).
// x broadcast via uniform LDG.128; partials combined through tiny smem tile.
#define NODES_PER_QUAD 16
__global__ void __launch_bounds__(256) proj_kernel(const float* __restrict__ x,
                            const float* __restrict__ w_rel,
                            const float* __restrict__ w_root) {
    __shared__ float s_part[2][4][2][DIM];   // [quad][kq][y/z][lane]
    int tid  = threadIdx.x;
    int lane = tid & 31;
    int warp = tid >> 5;
    int quad = warp >> 2;       // 0/1
    int kq   = warp & 3;        // k-quarter

    // zero scratch used by later kernels
    int gtid = blockIdx.x * 256 + tid;
    if (gtid < N_NODES) g_deg[gtid] = 0;
    if (gtid < N_GRAPHS * DIM) g_pooled[gtid] = 0.0f;

    // weights for this lane's output column, this warp's k-slice -> registers
    float wr[32], wo[32];
#pragma unroll
    for (int j = 0; j < 32; j++) {
        wr[j] = w_rel [(kq * 32 + j) * DIM + lane];
        wo[j] = w_root[(kq * 32 + j) * DIM + lane];
    }

    int base = blockIdx.x * (2 * NODES_PER_QUAD);

#pragma unroll 1
    for (int it = 0; it < NODES_PER_QUAD; ++it) {
        int node = base + quad * NODES_PER_QUAD + it;
        float ay = 0.0f, az = 0.0f;
        if (node < N_NODES) {
            const float4* xp = reinterpret_cast<const float4*>(
                x + (size_t)node * N_FEAT + kq * 32);
            float4 xv[8];
#pragma unroll
            for (int j = 0; j < 8; j++) xv[j] = xp[j];   // uniform broadcast
#pragma unroll
            for (int j = 0; j < 8; j++) {
                ay = fmaf(xv[j].x, wr[j*4+0], ay); az = fmaf(xv[j].x, wo[j*4+0], az);
                ay = fmaf(xv[j].y, wr[j*4+1], ay); az = fmaf(xv[j].y, wo[j*4+1], az);
                ay = fmaf(xv[j].z, wr[j*4+2], ay); az = fmaf(xv[j].z, wo[j*4+2], az);
                ay = fmaf(xv[j].w, wr[j*4+3], ay); az = fmaf(xv[j].w, wo[j*4+3], az);
            }
        }
        s_part[quad][kq][0][lane] = ay;
        s_part[quad][kq][1][lane] = az;
        __syncthreads();

        // warps 0..3 reduce the 4 partials: w0=A.y w1=A.z w2=B.y w3=B.z
        if (warp < 4) {
            int nq  = warp >> 1;
            int out = warp & 1;
            int n2  = base + nq * NODES_PER_QUAD + it;
            if (n2 < N_NODES) {
                float v = s_part[nq][0][out][lane] + s_part[nq][1][out][lane]
                        + s_part[nq][2][out][lane] + s_part[nq][3][out][lane];
                if (out == 0) g_y[n2 * DIM + lane] = v;
                else          g_z[n2 * DIM + lane] = v;
            }
        }
        __syncthreads();
    }
}

// ---------------- kernel 2: degree histogram ----------------
__global__ void hist_kernel(const int* __restrict__ ei_raw) {
    int e = blockIdx.x * blockDim.x + threadIdx.x;
    if (e >= N_EDGES) return;
    int dst = g_idx_is64 ? ei_raw[2 * (N_EDGES + e)] : ei_raw[N_EDGES + e];
    if ((unsigned)dst < N_NODES) atomicAdd(&g_deg[dst], 1);
}

// ---------------- kernel 3: single-block exclusive scan ----------------
__global__ void scan_kernel() {
    __shared__ int s[1024];
    const int CH = 49;                       // 1024*49 = 50176 >= 50000
    int t = threadIdx.x;
    int base = t * CH;
    int sum = 0;
    for (int j = 0; j < CH; j++) {
        int idx = base + j;
        if (idx < N_NODES) sum += g_deg[idx];
    }
    s[t] = sum;
    __syncthreads();
    for (int off = 1; off < 1024; off <<= 1) {
        int v = (t >= off) ? s[t - off] : 0;
        __syncthreads();
        s[t] += v;
        __syncthreads();
    }
    int run = s[t] - sum;                    // exclusive prefix
    for (int j = 0; j < CH; j++) {
        int idx = base + j;
        if (idx < N_NODES) {
            g_off[idx]    = run;
            g_cursor[idx] = run;
            run += g_deg[idx];
        }
    }
    if (t == 1023) g_off[N_NODES] = s[1023];
}

// ---------------- kernel 4: CSR fill ----------------
__global__ void fill_kernel(const int* __restrict__ ei_raw,
                            const float* __restrict__ ew) {
    int e = blockIdx.x * blockDim.x + threadIdx.x;
    if (e >= N_EDGES) return;
    int src, dst;
    if (g_idx_is64) {
        src = ei_raw[2 * e];
        dst = ei_raw[2 * (N_EDGES + e)];
    } else {
        src = ei_raw[e];
        dst = ei_raw[N_EDGES + e];
    }
    if ((unsigned)src >= N_NODES || (unsigned)dst >= N_NODES) return;
    int pos = atomicAdd(&g_cursor[dst], 1);
    g_csr[pos] = make_int2(src, __float_as_int(ew[e]));
}

// ---------------- kernel 5: gather + relu + graph pooling (fused) ----------
// warp per node, lane per output column. No atomics into agg at all.
__global__ void gather_kernel(const float* __restrict__ b_rel,
                              const int* __restrict__ batch_raw) {
    int warp = threadIdx.x >> 5;
    int lane = threadIdx.x & 31;
    int node = blockIdx.x * 8 + warp;
    if (node >= N_NODES) return;

    int off0 = g_off[node];
    int off1 = g_off[node + 1];

    float acc = 0.0f;
    int i = off0;
    for (; i + 1 < off1; i += 2) {           // 2-way ILP on L2 gathers
        int2 e0 = g_csr[i];
        int2 e1 = g_csr[i + 1];
        float y0 = g_y[e0.x * DIM + lane];
        float y1 = g_y[e1.x * DIM + lane];
        acc = fmaf(__int_as_float(e0.y), y0, acc);
        acc = fmaf(__int_as_float(e1.y), y1, acc);
    }
    if (i < off1) {
        int2 e0 = g_csr[i];
        acc = fmaf(__int_as_float(e0.y), g_y[e0.x * DIM + lane], acc);
    }

    float h = fmaxf(acc + g_z[node * DIM + lane] + b_rel[lane], 0.0f);

    int g = g_idx_is64 ? batch_raw[2 * node] : batch_raw[node];
    if ((unsigned)g < N_GRAPHS)
        atomicAdd(&g_pooled[g * DIM + lane], h);
}

// ---------------- kernel 6: head MLP + log_softmax ----------------
__global__ void head_kernel(const float* __restrict__ w_fc1,
                            const float* __restrict__ b_fc1,
                            const float* __restrict__ w_fc2,
                            const float* __restrict__ b_fc2,
                            float* __restrict__ out) {
    __shared__ float sp[DIM];
    __shared__ float sh2[DIM];
    int g = blockIdx.x;
    int lane = threadIdx.x;

    sp[lane] = g_pooled[g * DIM + lane];
    __syncwarp();

    float acc = b_fc1[lane];
#pragma unroll
    for (int j = 0; j < DIM; j++)
        acc = fmaf(sp[j], w_fc1[j * DIM + lane], acc);
    sh2[lane] = fmaxf(acc, 0.0f);
    __syncwarp();

    if (lane == 0) {
        float l0 = b_fc2[0], l1 = b_fc2[1];
#pragma unroll
        for (int k = 0; k < DIM; k++) {
            l0 = fmaf(sh2[k], w_fc2[k * 2 + 0], l0);
            l1 = fmaf(sh2[k], w_fc2[k * 2 + 1], l1);
        }
        float m = fmaxf(l0, l1);
        float lse = m + logf(expf(l0 - m) + expf(l1 - m));
        out[g * 2 + 0] = l0 - lse;
        out[g * 2 + 1] = l1 - lse;
    }
}

extern "C" void kernel_launch(void* const* d_in, const int* in_sizes, int n_in,
                              void* d_out, int out_size) {
    const float* x      = (const float*)d_in[0];
    const float* ew     = (const float*)d_in[1];
    const float* w_rel  = (const float*)d_in[2];
    const float* b_rel  = (const float*)d_in[3];
    const float* w_root = (const float*)d_in[4];
    const float* w_fc1  = (const float*)d_in[5];
    const float* b_fc1  = (const float*)d_in[6];
    const float* w_fc2  = (const float*)d_in[7];
    const float* b_fc2  = (const float*)d_in[8];
    const int*   ei     = (const int*)d_in[9];
    const int*   batch  = (const int*)d_in[10];
    float* out = (float*)d_out;

    detect_kernel<<<1, 256>>>(ei);
    // 1563 blocks x 32 nodes = 50016 >= 50000
    proj_kernel<<<(N_NODES + 2 * NODES_PER_QUAD - 1) / (2 * NODES_PER_QUAD), 256>>>(x, w_rel, w_root);
    hist_kernel<<<(N_EDGES + 255) / 256, 256>>>(ei);
    scan_kernel<<<1, 1024>>>();
    fill_kernel<<<(N_EDGES + 255) / 256, 256>>>(ei, ew);
    gather_kernel<<<(N_NODES + 7) / 8, 256>>>(b_rel, batch);
    head_kernel<<<N_GRAPHS, 32>>>(w_fc1, b_fc1, w_fc2, b_fc2, out);
}

// round 4
// speedup vs baseline: 1.5571x; 1.5571x over previous
#include <cuda_runtime.h>
#include <cuda_bf16.h>
#include <math.h>

#define N_NODES 50000
#define N_EDGES 800000
#define N_FEAT  128
#define DIM     32
#define N_GRAPHS 500
#define N_CLASSES 2

#define SCAN_BLK 1024
#define SCAN_NB  49          // 49*1024 = 50176 >= 50000

// ---------------- scratch (no allocations allowed) ----------------
__device__ float g_y[N_NODES * DIM];        // x @ w_rel
__device__ float g_z[N_NODES * DIM];        // x @ w_root
__device__ float g_pooled[N_GRAPHS * DIM];
__device__ int   g_deg[N_NODES];
__device__ int   g_off[N_NODES + 1];
__device__ int   g_cursor[N_NODES];
__device__ int   g_bsum[SCAN_NB];
__device__ int   g_boff[SCAN_NB];
__device__ int2  g_csr[N_EDGES];            // (src, weight bits) sorted by dst
__device__ int   g_idx_is64;                // 1 if index buffers are int64

// ---------------- kernel 0: detect index dtype ----------------
// int64 little-endian -> every odd 32-bit word is the hi word of id<50000 -> 0.
__global__ void detect_kernel(const int* __restrict__ ei_raw) {
    __shared__ int s_any;
    if (threadIdx.x == 0) s_any = 0;
    __syncthreads();
    if (ei_raw[threadIdx.x * 2 + 1] != 0) atomicOr(&s_any, 1);
    __syncthreads();
    if (threadIdx.x == 0) g_idx_is64 = s_any ? 0 : 1;
}

// ---------------- kernel 1: projection (weights in registers) ----------------
#define NODES_PER_QUAD 16
__global__ void __launch_bounds__(256) proj_kernel(const float* __restrict__ x,
                            const float* __restrict__ w_rel,
                            const float* __restrict__ w_root) {
    __shared__ float s_part[2][4][2][DIM];   // [quad][kq][y/z][lane]
    int tid  = threadIdx.x;
    int lane = tid & 31;
    int warp = tid >> 5;
    int quad = warp >> 2;       // 0/1
    int kq   = warp & 3;        // k-quarter

    // zero scratch used by later kernels
    int gtid = blockIdx.x * 256 + tid;
    if (gtid < N_NODES) g_deg[gtid] = 0;
    if (gtid < N_GRAPHS * DIM) g_pooled[gtid] = 0.0f;

    float wr[32], wo[32];
#pragma unroll
    for (int j = 0; j < 32; j++) {
        wr[j] = w_rel [(kq * 32 + j) * DIM + lane];
        wo[j] = w_root[(kq * 32 + j) * DIM + lane];
    }

    int base = blockIdx.x * (2 * NODES_PER_QUAD);

#pragma unroll 1
    for (int it = 0; it < NODES_PER_QUAD; ++it) {
        int node = base + quad * NODES_PER_QUAD + it;
        float ay = 0.0f, az = 0.0f;
        if (node < N_NODES) {
            const float4* xp = reinterpret_cast<const float4*>(
                x + (size_t)node * N_FEAT + kq * 32);
            float4 xv[8];
#pragma unroll
            for (int j = 0; j < 8; j++) xv[j] = xp[j];   // uniform broadcast
#pragma unroll
            for (int j = 0; j < 8; j++) {
                ay = fmaf(xv[j].x, wr[j*4+0], ay); az = fmaf(xv[j].x, wo[j*4+0], az);
                ay = fmaf(xv[j].y, wr[j*4+1], ay); az = fmaf(xv[j].y, wo[j*4+1], az);
                ay = fmaf(xv[j].z, wr[j*4+2], ay); az = fmaf(xv[j].z, wo[j*4+2], az);
                ay = fmaf(xv[j].w, wr[j*4+3], ay); az = fmaf(xv[j].w, wo[j*4+3], az);
            }
        }
        s_part[quad][kq][0][lane] = ay;
        s_part[quad][kq][1][lane] = az;
        __syncthreads();

        if (warp < 4) {
            int nq  = warp >> 1;
            int out = warp & 1;
            int n2  = base + nq * NODES_PER_QUAD + it;
            if (n2 < N_NODES) {
                float v = s_part[nq][0][out][lane] + s_part[nq][1][out][lane]
                        + s_part[nq][2][out][lane] + s_part[nq][3][out][lane];
                if (out == 0) g_y[n2 * DIM + lane] = v;
                else          g_z[n2 * DIM + lane] = v;
            }
        }
        __syncthreads();
    }
}

// ---------------- kernel 2: degree histogram ----------------
__global__ void hist_kernel(const int* __restrict__ ei_raw) {
    int e = blockIdx.x * blockDim.x + threadIdx.x;
    if (e >= N_EDGES) return;
    int dst = g_idx_is64 ? ei_raw[2 * (N_EDGES + e)] : ei_raw[N_EDGES + e];
    if ((unsigned)dst < N_NODES) atomicAdd(&g_deg[dst], 1);
}

// ---------------- kernel 3a: per-block reduce ----------------
__global__ void __launch_bounds__(SCAN_BLK) scan_reduce_kernel() {
    __shared__ int s[32];
    int idx = blockIdx.x * SCAN_BLK + threadIdx.x;
    int v = (idx < N_NODES) ? g_deg[idx] : 0;
#pragma unroll
    for (int o = 16; o > 0; o >>= 1) v += __shfl_down_sync(0xffffffffu, v, o);
    if ((threadIdx.x & 31) == 0) s[threadIdx.x >> 5] = v;
    __syncthreads();
    if (threadIdx.x < 32) {
        int w = s[threadIdx.x];
#pragma unroll
        for (int o = 16; o > 0; o >>= 1) w += __shfl_down_sync(0xffffffffu, w, o);
        if (threadIdx.x == 0) g_bsum[blockIdx.x] = w;
    }
}

// ---------------- kernel 3b: scan block sums (64 threads) ----------------
__global__ void scan_bsum_kernel() {
    __shared__ int s[64];
    int t = threadIdx.x;
    int v = (t < SCAN_NB) ? g_bsum[t] : 0;
    s[t] = v;
    __syncthreads();
#pragma unroll
    for (int o = 1; o < 64; o <<= 1) {
        int u = (t >= o) ? s[t - o] : 0;
        __syncthreads();
        s[t] += u;
        __syncthreads();
    }
    if (t < SCAN_NB) g_boff[t] = s[t] - v;   // exclusive
    if (t == 63) g_off[N_NODES] = s[63];
}

// ---------------- kernel 3c: local scan + add block offset ----------------
__global__ void __launch_bounds__(SCAN_BLK) scan_final_kernel() {
    __shared__ int s[SCAN_BLK];
    int t = threadIdx.x;
    int idx = blockIdx.x * SCAN_BLK + t;
    int v = (idx < N_NODES) ? g_deg[idx] : 0;
    s[t] = v;
    __syncthreads();
#pragma unroll
    for (int o = 1; o < SCAN_BLK; o <<= 1) {
        int u = (t >= o) ? s[t - o] : 0;
        __syncthreads();
        s[t] += u;
        __syncthreads();
    }
    if (idx < N_NODES) {
        int off = g_boff[blockIdx.x] + s[t] - v;  // exclusive
        g_off[idx]    = off;
        g_cursor[idx] = off;
    }
}

// ---------------- kernel 4: CSR fill ----------------
__global__ void fill_kernel(const int* __restrict__ ei_raw,
                            const float* __restrict__ ew) {
    int e = blockIdx.x * blockDim.x + threadIdx.x;
    if (e >= N_EDGES) return;
    int src, dst;
    if (g_idx_is64) {
        src = ei_raw[2 * e];
        dst = ei_raw[2 * (N_EDGES + e)];
    } else {
        src = ei_raw[e];
        dst = ei_raw[N_EDGES + e];
    }
    if ((unsigned)src >= N_NODES || (unsigned)dst >= N_NODES) return;
    int pos = atomicAdd(&g_cursor[dst], 1);
    g_csr[pos] = make_int2(src, __float_as_int(ew[e]));
}

// ---------------- kernel 5: gather + relu + graph pooling (fused) ----------
__global__ void gather_kernel(const float* __restrict__ b_rel,
                              const int* __restrict__ batch_raw) {
    int warp = threadIdx.x >> 5;
    int lane = threadIdx.x & 31;
    int node = blockIdx.x * 8 + warp;
    if (node >= N_NODES) return;

    int off0 = g_off[node];
    int off1 = g_off[node + 1];

    float acc = 0.0f;
    int i = off0;
    for (; i + 3 < off1; i += 4) {           // 4-way ILP on L2 gathers
        int2 e0 = g_csr[i];
        int2 e1 = g_csr[i + 1];
        int2 e2 = g_csr[i + 2];
        int2 e3 = g_csr[i + 3];
        float y0 = g_y[e0.x * DIM + lane];
        float y1 = g_y[e1.x * DIM + lane];
        float y2 = g_y[e2.x * DIM + lane];
        float y3 = g_y[e3.x * DIM + lane];
        acc = fmaf(__int_as_float(e0.y), y0, acc);
        acc = fmaf(__int_as_float(e1.y), y1, acc);
        acc = fmaf(__int_as_float(e2.y), y2, acc);
        acc = fmaf(__int_as_float(e3.y), y3, acc);
    }
    for (; i < off1; i++) {
        int2 e0 = g_csr[i];
        acc = fmaf(__int_as_float(e0.y), g_y[e0.x * DIM + lane], acc);
    }

    float h = fmaxf(acc + g_z[node * DIM + lane] + b_rel[lane], 0.0f);

    int g = g_idx_is64 ? batch_raw[2 * node] : batch_raw[node];
    if ((unsigned)g < N_GRAPHS)
        atomicAdd(&g_pooled[g * DIM + lane], h);
}

// ---------------- kernel 6: head MLP + log_softmax ----------------
__global__ void head_kernel(const float* __restrict__ w_fc1,
                            const float* __restrict__ b_fc1,
                            const float* __restrict__ w_fc2,
                            const float* __restrict__ b_fc2,
                            float* __restrict__ out) {
    __shared__ float sp[DIM];
    __shared__ float sh2[DIM];
    int g = blockIdx.x;
    int lane = threadIdx.x;

    sp[lane] = g_pooled[g * DIM + lane];
    __syncwarp();

    float acc = b_fc1[lane];
#pragma unroll
    for (int j = 0; j < DIM; j++)
        acc = fmaf(sp[j], w_fc1[j * DIM + lane], acc);
    sh2[lane] = fmaxf(acc, 0.0f);
    __syncwarp();

    if (lane == 0) {
        float l0 = b_fc2[0], l1 = b_fc2[1];
#pragma unroll
        for (int k = 0; k < DIM; k++) {
            l0 = fmaf(sh2[k], w_fc2[k * 2 + 0], l0);
            l1 = fmaf(sh2[k], w_fc2[k * 2 + 1], l1);
        }
        float m = fmaxf(l0, l1);
        float lse = m + logf(expf(l0 - m) + expf(l1 - m));
        out[g * 2 + 0] = l0 - lse;
        out[g * 2 + 1] = l1 - lse;
    }
}

extern "C" void kernel_launch(void* const* d_in, const int* in_sizes, int n_in,
                              void* d_out, int out_size) {
    const float* x      = (const float*)d_in[0];
    const float* ew     = (const float*)d_in[1];
    const float* w_rel  = (const float*)d_in[2];
    const float* b_rel  = (const float*)d_in[3];
    const float* w_root = (const float*)d_in[4];
    const float* w_fc1  = (const float*)d_in[5];
    const float* b_fc1  = (const float*)d_in[6];
    const float* w_fc2  = (const float*)d_in[7];
    const float* b_fc2  = (const float*)d_in[8];
    const int*   ei     = (const int*)d_in[9];
    const int*   batch  = (const int*)d_in[10];
    float* out = (float*)d_out;

    detect_kernel<<<1, 256>>>(ei);
    proj_kernel<<<(N_NODES + 2 * NODES_PER_QUAD - 1) / (2 * NODES_PER_QUAD), 256>>>(x, w_rel, w_root);
    hist_kernel<<<(N_EDGES + 255) / 256, 256>>>(ei);
    scan_reduce_kernel<<<SCAN_NB, SCAN_BLK>>>();
    scan_bsum_kernel<<<1, 64>>>();
    scan_final_kernel<<<SCAN_NB, SCAN_BLK>>>();
    fill_kernel<<<(N_EDGES + 255) / 256, 256>>>(ei, ew);
    gather_kernel<<<(N_NODES + 7) / 8, 256>>>(b_rel, batch);
    head_kernel<<<N_GRAPHS, 32>>>(w_fc1, b_fc1, w_fc2, b_fc2, out);
}

// round 7
// speedup vs baseline: 1.7463x; 1.1215x over previous
#include <cuda_runtime.h>
#include <cuda_bf16.h>
#include <math.h>

#define N_NODES 50000
#define N_EDGES 800000
#define N_FEAT  128
#define DIM     32
#define N_GRAPHS 500
#define N_CLASSES 2
#define CAP     64            // per-node bin capacity (P(deg>64) ~ 1e-20)

// ---------------- scratch (no allocations allowed) ----------------
__device__ float g_y[N_NODES * DIM];        // x @ w_rel
__device__ float g_z[N_NODES * DIM];        // x @ w_root
__device__ float g_agg[N_NODES * DIM];      // overflow-fallback accumulator
__device__ float g_pooled[N_GRAPHS * DIM];
__device__ int   g_deg[N_NODES];
__device__ int2  g_bin[N_NODES * CAP];      // (src, weight bits), 25.6 MB

// ---------------- kernel 1: projection + zero scratch ----------------
// 8 warps = 2 quads of 4 warps; each quad handles 16 nodes; each warp owns a
// 32-wide k-slice with its weight columns in registers. x via uniform LDG.128.
#define NODES_PER_QUAD 16
__global__ void __launch_bounds__(256) proj_kernel(const float* __restrict__ x,
                            const float* __restrict__ w_rel,
                            const float* __restrict__ w_root) {
    __shared__ float s_part[2][4][2][DIM];   // [quad][kq][y/z][lane]
    int tid  = threadIdx.x;
    int lane = tid & 31;
    int warp = tid >> 5;
    int quad = warp >> 2;
    int kq   = warp & 3;

    // zero scratch used by later kernels
    int gtid = blockIdx.x * 256 + tid;
    if (gtid < N_NODES) g_deg[gtid] = 0;
    if (gtid < N_GRAPHS * DIM) g_pooled[gtid] = 0.0f;
    if (gtid < N_NODES * DIM / 4)            // zero g_agg as float4
        reinterpret_cast<float4*>(g_agg)[gtid] = make_float4(0.f, 0.f, 0.f, 0.f);

    float wr[32], wo[32];
#pragma unroll
    for (int j = 0; j < 32; j++) {
        wr[j] = w_rel [(kq * 32 + j) * DIM + lane];
        wo[j] = w_root[(kq * 32 + j) * DIM + lane];
    }

    int base = blockIdx.x * (2 * NODES_PER_QUAD);

#pragma unroll 1
    for (int it = 0; it < NODES_PER_QUAD; ++it) {
        int node = base + quad * NODES_PER_QUAD + it;
        float ay = 0.0f, az = 0.0f;
        if (node < N_NODES) {
            const float4* xp = reinterpret_cast<const float4*>(
                x + (size_t)node * N_FEAT + kq * 32);
            float4 xv[8];
#pragma unroll
            for (int j = 0; j < 8; j++) xv[j] = xp[j];   // uniform broadcast
#pragma unroll
            for (int j = 0; j < 8; j++) {
                ay = fmaf(xv[j].x, wr[j*4+0], ay); az = fmaf(xv[j].x, wo[j*4+0], az);
                ay = fmaf(xv[j].y, wr[j*4+1], ay); az = fmaf(xv[j].y, wo[j*4+1], az);
                ay = fmaf(xv[j].z, wr[j*4+2], ay); az = fmaf(xv[j].z, wo[j*4+2], az);
                ay = fmaf(xv[j].w, wr[j*4+3], ay); az = fmaf(xv[j].w, wo[j*4+3], az);
            }
        }
        s_part[quad][kq][0][lane] = ay;
        s_part[quad][kq][1][lane] = az;
        __syncthreads();

        if (warp < 4) {
            int nq  = warp >> 1;
            int out = warp & 1;
            int n2  = base + nq * NODES_PER_QUAD + it;
            if (n2 < N_NODES) {
                float v = s_part[nq][0][out][lane] + s_part[nq][1][out][lane]
                        + s_part[nq][2][out][lane] + s_part[nq][3][out][lane];
                if (out == 0) g_y[n2 * DIM + lane] = v;
                else          g_z[n2 * DIM + lane] = v;
            }
        }
        __syncthreads();
    }
}

// ---------------- inline dtype detection helper -------------------------
// int64 little-endian: every odd 32-bit word is hi word of an id<50000 -> 0.
// With int32 random ids, 256 consecutive zero odd-words is impossible.
__device__ __forceinline__ bool detect_is64(const int* __restrict__ ei_raw,
                                            int tid) {
    int probe = ei_raw[(tid & 255) * 2 + 1];
    int nz = __syncthreads_count(probe != 0);   // block-wide, broadcast result
    return nz == 0;
}

// ---------------- kernel 2: binned CSR fill (no scan needed) ------------
__global__ void __launch_bounds__(256) fill_kernel(const int* __restrict__ ei_raw,
                            const float* __restrict__ ew) {
    bool is64 = detect_is64(ei_raw, threadIdx.x);
    int e = blockIdx.x * 256 + threadIdx.x;
    if (e >= N_EDGES) return;

    int src, dst;
    if (is64) {
        src = ei_raw[2 * e];
        dst = ei_raw[2 * (N_EDGES + e)];
    } else {
        src = ei_raw[e];
        dst = ei_raw[N_EDGES + e];
    }
    float w = ew[e];                         // issue before the atomic
    if ((unsigned)src >= N_NODES || (unsigned)dst >= N_NODES) return;

    int pos = atomicAdd(&g_deg[dst], 1);
    if (pos < CAP) {
        g_bin[dst * CAP + pos] = make_int2(src, __float_as_int(w));
    } else {
        // astronomically rare overflow: direct reduction into g_agg
        const float4* yp = reinterpret_cast<const float4*>(g_y) + src * 8;
        float4* ap = reinterpret_cast<float4*>(g_agg) + dst * 8;
#pragma unroll
        for (int s = 0; s < 8; s++) {
            float4 v = yp[s];
            asm volatile("red.global.add.v4.f32 [%0], {%1,%2,%3,%4};"
                         :: "l"(ap + s), "f"(v.x*w), "f"(v.y*w), "f"(v.z*w), "f"(v.w*w)
                         : "memory");
        }
    }
}

// ---------------- kernel 3: gather + relu + graph pooling (fused) -------
// warp per node, lane per output column.
__global__ void __launch_bounds__(256) gather_kernel(const float* __restrict__ b_rel,
                              const int* __restrict__ batch_raw,
                              const int* __restrict__ ei_raw) {
    bool is64 = detect_is64(ei_raw, threadIdx.x);
    int warp = threadIdx.x >> 5;
    int lane = threadIdx.x & 31;
    int node = blockIdx.x * 8 + warp;
    if (node >= N_NODES) return;

    int deg = g_deg[node];
    if (deg > CAP) deg = CAP;

    const int4* bp = reinterpret_cast<const int4*>(g_bin + node * CAP);

    float acc = g_agg[node * DIM + lane];    // overflow fallback (usually 0)
    int i = 0;
    for (; i + 3 < deg; i += 4) {            // 2 int4 loads = 4 edges
        int4 p0 = bp[i >> 1];
        int4 p1 = bp[(i >> 1) + 1];
        float y0 = g_y[p0.x * DIM + lane];
        float y1 = g_y[p0.z * DIM + lane];
        float y2 = g_y[p1.x * DIM + lane];
        float y3 = g_y[p1.z * DIM + lane];
        acc = fmaf(__int_as_float(p0.y), y0, acc);
        acc = fmaf(__int_as_float(p0.w), y1, acc);
        acc = fmaf(__int_as_float(p1.y), y2, acc);
        acc = fmaf(__int_as_float(p1.w), y3, acc);
    }
    for (; i < deg; i++) {
        int2 e0 = g_bin[node * CAP + i];
        acc = fmaf(__int_as_float(e0.y), g_y[e0.x * DIM + lane], acc);
    }

    float h = fmaxf(acc + g_z[node * DIM + lane] + b_rel[lane], 0.0f);

    int g = is64 ? batch_raw[2 * node] : batch_raw[node];
    if ((unsigned)g < N_GRAPHS)
        atomicAdd(&g_pooled[g * DIM + lane], h);
}

// ---------------- kernel 4: head MLP + log_softmax ----------------------
__global__ void head_kernel(const float* __restrict__ w_fc1,
                            const float* __restrict__ b_fc1,
                            const float* __restrict__ w_fc2,
                            const float* __restrict__ b_fc2,
                            float* __restrict__ out) {
    __shared__ float sp[DIM];
    __shared__ float sh2[DIM];
    int g = blockIdx.x;
    int lane = threadIdx.x;

    sp[lane] = g_pooled[g * DIM + lane];
    __syncwarp();

    float acc = b_fc1[lane];
#pragma unroll
    for (int j = 0; j < DIM; j++)
        acc = fmaf(sp[j], w_fc1[j * DIM + lane], acc);
    sh2[lane] = fmaxf(acc, 0.0f);
    __syncwarp();

    if (lane == 0) {
        float l0 = b_fc2[0], l1 = b_fc2[1];
#pragma unroll
        for (int k = 0; k < DIM; k++) {
            l0 = fmaf(sh2[k], w_fc2[k * 2 + 0], l0);
            l1 = fmaf(sh2[k], w_fc2[k * 2 + 1], l1);
        }
        float m = fmaxf(l0, l1);
        float lse = m + logf(expf(l0 - m) + expf(l1 - m));
        out[g * 2 + 0] = l0 - lse;
        out[g * 2 + 1] = l1 - lse;
    }
}

extern "C" void kernel_launch(void* const* d_in, const int* in_sizes, int n_in,
                              void* d_out, int out_size) {
    const float* x      = (const float*)d_in[0];
    const float* ew     = (const float*)d_in[1];
    const float* w_rel  = (const float*)d_in[2];
    const float* b_rel  = (const float*)d_in[3];
    const float* w_root = (const float*)d_in[4];
    const float* w_fc1  = (const float*)d_in[5];
    const float* b_fc1  = (const float*)d_in[6];
    const float* w_fc2  = (const float*)d_in[7];
    const float* b_fc2  = (const float*)d_in[8];
    const int*   ei     = (const int*)d_in[9];
    const int*   batch  = (const int*)d_in[10];
    float* out = (float*)d_out;

    proj_kernel<<<(N_NODES + 2 * NODES_PER_QUAD - 1) / (2 * NODES_PER_QUAD), 256>>>(x, w_rel, w_root);
    fill_kernel<<<(N_EDGES + 255) / 256, 256>>>(ei, ew);
    gather_kernel<<<(N_NODES + 7) / 8, 256>>>(b_rel, batch, ei);
    head_kernel<<<N_GRAPHS, 32>>>(w_fc1, b_fc1, w_fc2, b_fc2, out);
}

// round 8
// speedup vs baseline: 2.0762x; 1.1889x over previous
#include <cuda_runtime.h>
#include <cuda_bf16.h>
#include <math.h>

#define N_NODES 50000
#define N_EDGES 800000
#define N_FEAT  128
#define DIM     32
#define N_GRAPHS 500
#define N_CLASSES 2
#define CAP     64            // per-node bin capacity (P(deg>64) ~ 1e-20)

// ---------------- scratch (no allocations allowed) ----------------
__device__ float g_y[N_NODES * DIM];        // x @ w_rel
__device__ float g_z[N_NODES * DIM];        // x @ w_root
__device__ float g_agg[N_NODES * DIM];      // overflow-fallback accumulator
__device__ float g_pooled[N_GRAPHS * DIM];
__device__ int   g_deg[N_NODES];
__device__ int2  g_bin[N_NODES * CAP];      // (src, weight bits), 25.6 MB

// packed f32x2 fma: acc = a * b + acc  (two fp32 lanes per instruction)
#define FMA2(acc, a, b) \
    asm("fma.rn.f32x2 %0, %1, %2, %0;" : "+l"(acc) : "l"(a), "l"(b))

__device__ __forceinline__ float f32x2_hsum(unsigned long long v) {
    unsigned lo, hi;
    asm("mov.b64 {%0,%1}, %2;" : "=r"(lo), "=r"(hi) : "l"(v));
    return __uint_as_float(lo) + __uint_as_float(hi);
}

__device__ __forceinline__ unsigned long long f32x2_pack(float a, float b) {
    unsigned long long r;
    asm("mov.b64 %0, {%1,%2};" : "=l"(r) : "r"(__float_as_uint(a)), "r"(__float_as_uint(b)));
    return r;
}

// ---------------- kernel Z: zero scratch (runs on side stream) ----------
__global__ void __launch_bounds__(256) zero_kernel() {
    int i = blockIdx.x * 256 + threadIdx.x;
    if (i < N_NODES * DIM / 4)
        reinterpret_cast<float4*>(g_agg)[i] = make_float4(0.f, 0.f, 0.f, 0.f);
    if (i < N_NODES) g_deg[i] = 0;
    if (i < N_GRAPHS * DIM) g_pooled[i] = 0.0f;
}

// ---------------- kernel 1: projection (f32x2, weights in registers) ----
// 8 warps = 2 quads; each quad handles 16 nodes; each warp owns a 32-wide
// k-slice. x pairs arrive pre-packed via ulonglong2 loads -> FFMA2 directly.
#define NODES_PER_QUAD 16
__global__ void __launch_bounds__(256) proj_kernel(const float* __restrict__ x,
                            const float* __restrict__ w_rel,
                            const float* __restrict__ w_root) {
    __shared__ float s_part[2][4][2][DIM];   // [quad][kq][y/z][lane]
    int tid  = threadIdx.x;
    int lane = tid & 31;
    int warp = tid >> 5;
    int quad = warp >> 2;
    int kq   = warp & 3;

    // weight pairs (k, k+1) for this lane's output column, packed as f32x2
    unsigned long long wpy[16], wpz[16];
#pragma unroll
    for (int p = 0; p < 16; p++) {
        int k0 = (kq * 32 + 2 * p) * DIM + lane;
        wpy[p] = f32x2_pack(w_rel [k0], w_rel [k0 + DIM]);
        wpz[p] = f32x2_pack(w_root[k0], w_root[k0 + DIM]);
    }

    int base = blockIdx.x * (2 * NODES_PER_QUAD);

#pragma unroll 1
    for (int it = 0; it < NODES_PER_QUAD; ++it) {
        int node = base + quad * NODES_PER_QUAD + it;
        unsigned long long accY = 0ull, accZ = 0ull;   // (0.f, 0.f)
        if (node < N_NODES) {
            const ulonglong2* xp = reinterpret_cast<const ulonglong2*>(
                x + (size_t)node * N_FEAT + kq * 32);
            ulonglong2 xv[8];                // 32 floats = 16 packed pairs
#pragma unroll
            for (int j = 0; j < 8; j++) xv[j] = xp[j];   // uniform broadcast
#pragma unroll
            for (int j = 0; j < 8; j++) {
                FMA2(accY, xv[j].x, wpy[2 * j]);
                FMA2(accZ, xv[j].x, wpz[2 * j]);
                FMA2(accY, xv[j].y, wpy[2 * j + 1]);
                FMA2(accZ, xv[j].y, wpz[2 * j + 1]);
            }
        }
        s_part[quad][kq][0][lane] = f32x2_hsum(accY);
        s_part[quad][kq][1][lane] = f32x2_hsum(accZ);
        __syncthreads();

        if (warp < 4) {
            int nq  = warp >> 1;
            int out = warp & 1;
            int n2  = base + nq * NODES_PER_QUAD + it;
            if (n2 < N_NODES) {
                float v = s_part[nq][0][out][lane] + s_part[nq][1][out][lane]
                        + s_part[nq][2][out][lane] + s_part[nq][3][out][lane];
                if (out == 0) g_y[n2 * DIM + lane] = v;
                else          g_z[n2 * DIM + lane] = v;
            }
        }
        __syncthreads();
    }
}

// ---------------- inline dtype detection helper -------------------------
// int64 little-endian: every odd 32-bit word is hi word of an id<50000 -> 0.
__device__ __forceinline__ bool detect_is64(const int* __restrict__ ei_raw,
                                            int tid) {
    int probe = ei_raw[(tid & 255) * 2 + 1];
    int nz = __syncthreads_count(probe != 0);   // block-wide, broadcast result
    return nz == 0;
}

// ---------------- kernel 2: binned CSR fill (no scan needed) ------------
__global__ void __launch_bounds__(256) fill_kernel(const int* __restrict__ ei_raw,
                            const float* __restrict__ ew) {
    bool is64 = detect_is64(ei_raw, threadIdx.x);
    int e = blockIdx.x * 256 + threadIdx.x;
    if (e >= N_EDGES) return;

    int src, dst;
    if (is64) {
        src = ei_raw[2 * e];
        dst = ei_raw[2 * (N_EDGES + e)];
    } else {
        src = ei_raw[e];
        dst = ei_raw[N_EDGES + e];
    }
    float w = ew[e];                         // issue before the atomic
    if ((unsigned)src >= N_NODES || (unsigned)dst >= N_NODES) return;

    int pos = atomicAdd(&g_deg[dst], 1);
    if (pos < CAP) {
        g_bin[dst * CAP + pos] = make_int2(src, __float_as_int(w));
    } else {
        // astronomically rare overflow: direct reduction into g_agg
        const float4* yp = reinterpret_cast<const float4*>(g_y) + src * 8;
        float4* ap = reinterpret_cast<float4*>(g_agg) + dst * 8;
#pragma unroll
        for (int s = 0; s < 8; s++) {
            float4 v = yp[s];
            asm volatile("red.global.add.v4.f32 [%0], {%1,%2,%3,%4};"
                         :: "l"(ap + s), "f"(v.x*w), "f"(v.y*w), "f"(v.z*w), "f"(v.w*w)
                         : "memory");
        }
    }
}

// ---------------- kernel 3: gather + relu + graph pooling (fused) -------
// warp per node, lane per output column.
__global__ void __launch_bounds__(256) gather_kernel(const float* __restrict__ b_rel,
                              const int* __restrict__ batch_raw,
                              const int* __restrict__ ei_raw) {
    bool is64 = detect_is64(ei_raw, threadIdx.x);
    int warp = threadIdx.x >> 5;
    int lane = threadIdx.x & 31;
    int node = blockIdx.x * 8 + warp;
    if (node >= N_NODES) return;

    int deg = g_deg[node];
    if (deg > CAP) deg = CAP;

    const int4* bp = reinterpret_cast<const int4*>(g_bin + node * CAP);

    float acc = g_agg[node * DIM + lane];    // overflow fallback (usually 0)
    int i = 0;
    for (; i + 3 < deg; i += 4) {            // 2 int4 loads = 4 edges
        int4 p0 = bp[i >> 1];
        int4 p1 = bp[(i >> 1) + 1];
        float y0 = g_y[p0.x * DIM + lane];
        float y1 = g_y[p0.z * DIM + lane];
        float y2 = g_y[p1.x * DIM + lane];
        float y3 = g_y[p1.z * DIM + lane];
        acc = fmaf(__int_as_float(p0.y), y0, acc);
        acc = fmaf(__int_as_float(p0.w), y1, acc);
        acc = fmaf(__int_as_float(p1.y), y2, acc);
        acc = fmaf(__int_as_float(p1.w), y3, acc);
    }
    for (; i < deg; i++) {
        int2 e0 = g_bin[node * CAP + i];
        acc = fmaf(__int_as_float(e0.y), g_y[e0.x * DIM + lane], acc);
    }

    float h = fmaxf(acc + g_z[node * DIM + lane] + b_rel[lane], 0.0f);

    int g = is64 ? batch_raw[2 * node] : batch_raw[node];
    if ((unsigned)g < N_GRAPHS)
        atomicAdd(&g_pooled[g * DIM + lane], h);
}

// ---------------- kernel 4: head MLP + log_softmax (warp per graph) -----
__global__ void __launch_bounds__(256) head_kernel(const float* __restrict__ w_fc1,
                            const float* __restrict__ b_fc1,
                            const float* __restrict__ w_fc2,
                            const float* __restrict__ b_fc2,
                            float* __restrict__ out) {
    int warp = threadIdx.x >> 5;
    int lane = threadIdx.x & 31;
    int g = blockIdx.x * 8 + warp;
    if (g >= N_GRAPHS) return;

    float p = g_pooled[g * DIM + lane];

    float acc = b_fc1[lane];
#pragma unroll
    for (int j = 0; j < DIM; j++) {
        float pj = __shfl_sync(0xffffffffu, p, j);
        acc = fmaf(pj, w_fc1[j * DIM + lane], acc);
    }
    float h2 = fmaxf(acc, 0.0f);

    float2 wv = reinterpret_cast<const float2*>(w_fc2)[lane];  // [lane][0..1]
    float l0 = h2 * wv.x;
    float l1 = h2 * wv.y;
#pragma unroll
    for (int o = 16; o > 0; o >>= 1) {
        l0 += __shfl_xor_sync(0xffffffffu, l0, o);
        l1 += __shfl_xor_sync(0xffffffffu, l1, o);
    }

    if (lane == 0) {
        l0 += b_fc2[0];
        l1 += b_fc2[1];
        float m = fmaxf(l0, l1);
        float lse = m + logf(expf(l0 - m) + expf(l1 - m));
        out[g * 2 + 0] = l0 - lse;
        out[g * 2 + 1] = l1 - lse;
    }
}

extern "C" void kernel_launch(void* const* d_in, const int* in_sizes, int n_in,
                              void* d_out, int out_size) {
    const float* x      = (const float*)d_in[0];
    const float* ew     = (const float*)d_in[1];
    const float* w_rel  = (const float*)d_in[2];
    const float* b_rel  = (const float*)d_in[3];
    const float* w_root = (const float*)d_in[4];
    const float* w_fc1  = (const float*)d_in[5];
    const float* b_fc1  = (const float*)d_in[6];
    const float* w_fc2  = (const float*)d_in[7];
    const float* b_fc2  = (const float*)d_in[8];
    const int*   ei     = (const int*)d_in[9];
    const int*   batch  = (const int*)d_in[10];
    float* out = (float*)d_out;

    // lazily created once (host-side resources, no device memory)
    static cudaStream_t s2 = 0;
    static cudaEvent_t evA = 0, evB = 0;
    if (!s2) {
        cudaStreamCreateWithFlags(&s2, cudaStreamNonBlocking);
        cudaEventCreateWithFlags(&evA, cudaEventDisableTiming);
        cudaEventCreateWithFlags(&evB, cudaEventDisableTiming);
    }

    // fork: side stream does zero -> fill, main stream does proj (disjoint data)
    cudaEventRecord(evA, 0);
    cudaStreamWaitEvent(s2, evA, 0);

    proj_kernel<<<(N_NODES + 2 * NODES_PER_QUAD - 1) / (2 * NODES_PER_QUAD), 256>>>(x, w_rel, w_root);

    zero_kernel<<<(N_NODES * DIM / 4 + 255) / 256, 256, 0, s2>>>();
    fill_kernel<<<(N_EDGES + 255) / 256, 256, 0, s2>>>(ei, ew);

    // join
    cudaEventRecord(evB, s2);
    cudaStreamWaitEvent(0, evB, 0);

    gather_kernel<<<(N_NODES + 7) / 8, 256>>>(b_rel, batch, ei);
    head_kernel<<<(N_GRAPHS + 7) / 8, 256>>>(w_fc1, b_fc1, w_fc2, b_fc2, out);
}